// round 9
// baseline (speedup 1.0000x reference)
#include <cuda_runtime.h>
#include <cuda_fp16.h>

// ---------------------------------------------------------------------------
// InterpolatingBSpline2d, round 8: single fused kernel; gather math slimmed.
//
// Gather audit (R7): per warp-batch ~176 issues, of which 64 were scalar
// F2F half->float conversions. The crossbar (random-gather conflicts) costs
// ~19.5us and can't drop without byte-level changes, but the ~10us of poorly
// overlapped issue work can: do the y-dot in HALF2 (HMUL2/HFMA2), convert
// only per-dx RESULTS to fp32 (8 F2F/point vs 64), accumulate x in fp32.
// Expected added error ~2.5e-4 RMS on top of 3.86e-4 storage -> ~5e-4 total.
//
// Prologue (R7, de-serialized in-place Thomas):
//   stage1: 256 threads, one (c,my) chain each, plain memory ops.
//   stage2: 264 threads (t=4*jx+c), plain loads + volatile copy0 half stores.
//   copy1 = copy0 shifted one y-slot via block-wide uint2 smem copy.
// Unified in-place smem layout: fp32 slot U(c,jx,my) at float index
//   (c&2 ? 8712 : 0) + jx*132 + 2*my + (c&1); halfs overwrite with >=2 slack.
// ---------------------------------------------------------------------------

#define M_GRID   64
#define NP2      66
#define NINNER   62
#define NCH      4
#define ROW_F    132                      // floats per (jx, copy) row = 528 B
#define NSLOT    (NP2 * NP2)              // 4356 (x,y) slots per copy
#define COPY_HALFS (NSLOT * NCH)          // 17424 halfs = 34,848 B per copy
#define COPY_F   (COPY_HALFS / 2)         // 8712 floats per copy region
#define SMEM_BYTES (2 * COPY_HALFS * 2)   // 69,696

// ---- compile-time Thomas factors ------------------------------------------
struct Fac { float cp[NINNER]; float invden[NINNER]; };

constexpr Fac make_fac() {
    Fac f{};
    const float B = 2.0f / 3.0f, A = 1.0f / 6.0f;
    float c = A / B;
    f.cp[0] = c;
    f.invden[0] = 1.0f / B;
    for (int m = 1; m < NINNER; ++m) {
        float den = B - A * c;
        float inv = 1.0f / den;
        c = A * inv;
        f.cp[m] = c;
        f.invden[m] = inv;
    }
    return f;
}
__constant__ Fac FAC = make_fac();

__device__ __forceinline__ unsigned short f2h(float v)
{
    return __half_as_ushort(__float2half_rn(v));
}

__device__ __forceinline__ __half2 u2h(unsigned v)
{
    return *reinterpret_cast<const __half2*>(&v);
}

__global__ void __launch_bounds__(1024, 2) bspline_fused(
    const float* __restrict__ data,
    const float2* __restrict__ u,
    float4* __restrict__ out, int n)
{
    extern __shared__ __align__(16) float sf[];     // 69,696 B
    __half* sh = reinterpret_cast<__half*>(sf);
    const int t = threadIdx.x;
    const float S = 1.0f / 6.0f;

    // ======== stage 1: solve along x (256 threads, one (c,my) chain) ========
    if (t < 256) {
        const int c  = t >> 6;
        const int my = t & 63;
        const float* src = data + c * (M_GRID * M_GRID) + my;   // stride 64
        float* B = sf + ((c & 2) ? COPY_F : 0) + 2 * my + (c & 1);

        float d0 = src[0];
        float a  = (src[64] - d0 * S) * FAC.invden[0];
        B[0] = a;                                   // dp[0]
#pragma unroll
        for (int m = 1; m <= 60; ++m) {
            a = (src[(m + 1) * 64] - a * S) * FAC.invden[m];
            B[m * ROW_F] = a;                       // dp[m]
        }
        float d63 = src[63 * 64];
        a = (src[62 * 64] - d63 * S - a * S) * FAC.invden[61];  // dp[61]

        float z = a;                                // x63
        B[65 * ROW_F] = 2.0f * d63 - z;
        B[64 * ROW_F] = d63;
        B[63 * ROW_F] = z;
#pragma unroll
        for (int m = 60; m >= 0; --m) {
            z = B[m * ROW_F] - FAC.cp[m] * z;       // read dp[m], emit x_{m+2}
            B[(m + 2) * ROW_F] = z;                 // slack-2, own-thread
        }
        B[ROW_F] = d0;                              // x1
        B[0]     = 2.0f * d0 - z;                   // x0 (z holds x2)
    }
    __syncthreads();

    // ======== stage 2: solve along y (264 threads, t = 4*jx + c) ========
    if (t < NCH * NP2) {
        const int jx = t >> 2, c = t & 3;
        const float* R = sf + ((c & 2) ? COPY_F : 0) + jx * ROW_F + (c & 1);
        float* W = const_cast<float*>(R);
        volatile unsigned short* T =
            reinterpret_cast<volatile unsigned short*>(sh);
        const int r0 = jx * (NP2 * NCH) + c;

        float d0 = R[0];
        float carry = (R[2] - d0 * S) * FAC.invden[0];
        W[0] = carry;                               // dp[0]
#pragma unroll
        for (int m = 1; m <= 60; ++m) {
            carry = (R[(m + 1) * 2] - carry * S) * FAC.invden[m];
            W[m * 2] = carry;                       // dp[m]
        }
        float s62 = R[62 * 2], d63 = R[63 * 2];
        carry = (s62 - d63 * S - carry * S) * FAC.invden[61];   // dp[61]

        float z = carry;                            // x63
        T[r0 + 65 * 4] = f2h(2.0f * d63 - z);       // y=65
        T[r0 + 64 * 4] = f2h(d63);                  // y=64
        T[r0 + 63 * 4] = f2h(z);                    // y=63
#pragma unroll
        for (int m = 60; m >= 0; --m) {
            z = R[m * 2] - FAC.cp[m] * z;
            T[r0 + (m + 2) * 4] = f2h(z);           // clobbers dp[m+2]: slack 2
        }
        T[r0 + 4] = f2h(d0);                        // y=1
        T[r0]     = f2h(2.0f * d0 - z);             // y=0 (z holds x2)
    }
    __syncthreads();

    // ======== copy1 = copy0 shifted one y-slot (8B granules) ========
    {
        uint2* s64 = reinterpret_cast<uint2*>(sf);
        for (int j = t; j < NSLOT - 1; j += blockDim.x)
            s64[NSLOT + j] = s64[j + 1];
    }
    __syncthreads();

    // ======== gather: half2 y-dot, fp32 x-accumulate ========
    int stride = gridDim.x * blockDim.x;
    for (int i = blockIdx.x * blockDim.x + t; i < n; i += stride) {
        float2 p = u[i];
        float uxn = p.x * 63.0f;
        float fx  = floorf(uxn);
        int   ix  = (int)fx;
        float tx  = uxn - fx;
        if (uxn < 0.0f)   { ix = 0;  tx = uxn; }
        if (uxn >= 62.0f) { ix = 62; tx = uxn - 62.0f; }

        float uyn = p.y * 63.0f;
        float fy  = floorf(uyn);
        int   iy  = (int)fy;
        float ty  = uyn - fy;
        if (uyn < 0.0f)   { iy = 0;  ty = uyn; }
        if (uyn >= 62.0f) { iy = 62; ty = uyn - 62.0f; }

        float wx0 = ((-S * tx + 0.5f) * tx - 0.5f) * tx + S;
        float wx1 = ((0.5f * tx - 1.0f) * tx) * tx + (2.0f / 3.0f);
        float wx2 = ((-0.5f * tx + 0.5f) * tx + 0.5f) * tx + S;
        float wx3 = (S * tx) * tx * tx;

        float wy0 = ((-S * ty + 0.5f) * ty - 0.5f) * ty + S;
        float wy1 = ((0.5f * ty - 1.0f) * ty) * ty + (2.0f / 3.0f);
        float wy2 = ((-0.5f * ty + 0.5f) * ty + 0.5f) * ty + S;
        float wy3 = (S * ty) * ty * ty;

        __half2 wy0h = __float2half2_rn(wy0);
        __half2 wy1h = __float2half2_rn(wy1);
        __half2 wy2h = __float2half2_rn(wy2);
        __half2 wy3h = __float2half2_rn(wy3);

        int iy2 = iy & ~1;
        const uint4* bp = reinterpret_cast<const uint4*>(
            sh + (iy & 1) * COPY_HALFS + (ix * NP2 + iy2) * NCH);

        float acc0 = 0.0f, acc1 = 0.0f, acc2 = 0.0f, acc3 = 0.0f;
#pragma unroll
        for (int dx = 0; dx < 4; ++dx) {
            uint4 qa = bp[dx * 33];        // y-taps 0,1 (each: c01, c23)
            uint4 qb = bp[dx * 33 + 1];    // y-taps 2,3

            // y-dot in half2 over channel pairs
            __half2 r01 = __hmul2(u2h(qa.x), wy0h);       // tap0 c01
            r01 = __hfma2(u2h(qa.z), wy1h, r01);          // tap1 c01
            r01 = __hfma2(u2h(qb.x), wy2h, r01);          // tap2 c01
            r01 = __hfma2(u2h(qb.z), wy3h, r01);          // tap3 c01

            __half2 r23 = __hmul2(u2h(qa.y), wy0h);       // tap0 c23
            r23 = __hfma2(u2h(qa.w), wy1h, r23);          // tap1 c23
            r23 = __hfma2(u2h(qb.y), wy2h, r23);          // tap2 c23
            r23 = __hfma2(u2h(qb.w), wy3h, r23);          // tap3 c23

            float2 f01 = __half22float2(r01);
            float2 f23 = __half22float2(r23);

            float wx = (dx == 0) ? wx0 : (dx == 1) ? wx1 : (dx == 2) ? wx2 : wx3;
            acc0 += wx * f01.x;
            acc1 += wx * f01.y;
            acc2 += wx * f23.x;
            acc3 += wx * f23.y;
        }
        out[i] = make_float4(acc0, acc1, acc2, acc3);
    }
}

extern "C" void kernel_launch(void* const* d_in, const int* in_sizes, int n_in,
                              void* d_out, int out_size)
{
    const float2* u    = (const float2*)d_in[0];
    const float*  data = (const float*)d_in[1];
    int n = in_sizes[0] / 2;

    cudaFuncSetAttribute(bspline_fused,
                         cudaFuncAttributeMaxDynamicSharedMemorySize, SMEM_BYTES);

    bspline_fused<<<296, 1024, SMEM_BYTES>>>(data, u, (float4*)d_out, n);
}